// round 1
// baseline (speedup 1.0000x reference)
#include <cuda_runtime.h>
#include <math.h>

// Problem constants
#define SEQ   1000
#define IND   100
#define POOLW 10
#define HID   64
#define OUTD  5
#define NB    16
#define BATCH 65536

// Tiling
#define BM     128            // batch rows per CTA
#define KC     64             // k-chunk = 4 i's x 16 basis
#define NCHUNK 25             // 1600 / 64
#define NTHR   128

// smem layout (floats):
//   xp  [100][128]              offset 0      (12800)  -- reused for c2s in phase 3
//   sA  [64][68]                offset 12800  (4352)
//   sB  [64][128]               offset 17152  (8192)
//   sh  [128][65]               offset 12800  (8320, reuses sA+sB)
#define OFF_XP 0
#define OFF_SA 12800
#define OFF_SB (12800 + 64*68)
#define OFF_SH 12800
#define SMEM_FLOATS (12800 + 64*68 + 64*128)
#define SMEM_BYTES  (SMEM_FLOATS * 4)

__device__ __forceinline__ unsigned long long pk2(float lo, float hi) {
    unsigned long long r;
    asm("mov.b64 %0, {%1,%2};" : "=l"(r) : "f"(lo), "f"(hi));
    return r;
}
__device__ __forceinline__ void upk2(unsigned long long v, float& lo, float& hi) {
    asm("mov.b64 {%0,%1}, %2;" : "=f"(lo), "=f"(hi) : "l"(v));
}
__device__ __forceinline__ void fma2(unsigned long long& d, unsigned long long a, unsigned long long b) {
    asm("fma.rn.f32x2 %0, %1, %2, %0;" : "+l"(d) : "l"(a), "l"(b));
}

extern __shared__ float smem[];

__global__ __launch_bounds__(NTHR, 2)
void kan_fused_kernel(const float* __restrict__ x,
                      const float* __restrict__ c1,    // [64][100][16] = [64][1600]
                      const float* __restrict__ c2,    // [5][64][16]   = [5][1024]
                      const float* __restrict__ centers,
                      float* __restrict__ out)         // [BATCH][5]
{
    const int t   = threadIdx.x;
    const int blk = blockIdx.x;

    float* xp  = smem + OFF_XP;   // [i][row], row-stride 1 across threads
    float* sA  = smem + OFF_SA;   // [k][o], pad 68
    float* sB  = smem + OFF_SB;   // [k][row]
    float* sh  = smem + OFF_SH;   // [row][65]
    float* c2s = smem + OFF_XP;   // [q][j][n] flat copy of c2 (phase 3)

    const float K2 = -0.5f / 0.36f;

    float ctr[NB];
    #pragma unroll
    for (int n = 0; n < NB; n++) ctr[n] = __ldg(centers + n);

    // ---------------- Phase 1: pool 1000 -> 100 ----------------
    const float* xblk = x + (size_t)blk * BM * SEQ;
    for (int p = t; p < BM * IND; p += NTHR) {
        int row = p / IND;
        int i   = p - row * IND;
        const float* xr = xblk + row * SEQ + i * POOLW;
        float s = 0.f;
        #pragma unroll
        for (int m = 0; m < POOLW; m++) s += __ldg(xr + m);
        xp[i * BM + row] = s * (1.0f / POOLW);
    }
    __syncthreads();

    // per-row stats (thread t owns row t); ddof=1, eps outside sqrt
    float mu = 0.f;
    #pragma unroll 10
    for (int i = 0; i < IND; i++) mu += xp[i * BM + t];
    mu *= (1.0f / IND);
    float var = 0.f;
    #pragma unroll 10
    for (int i = 0; i < IND; i++) { float d = xp[i * BM + t] - mu; var += d * d; }
    var *= (1.0f / (IND - 1));
    const float sc = 1.0f / (sqrtf(var) + 1e-6f);

    // ---------------- Phase 2: basis + GEMM1 (fused, K-chunked) ----------------
    const int tr = (t & 15) * 8;   // row base of 8x8 register tile
    const int tc = (t >> 4) * 8;   // col base

    unsigned long long acc[8][4];
    #pragma unroll
    for (int r = 0; r < 8; r++)
        #pragma unroll
        for (int c4 = 0; c4 < 4; c4++) acc[r][c4] = 0ull;

    for (int ch = 0; ch < NCHUNK; ch++) {
        __syncthreads();   // previous GEMM reads of sA/sB complete

        // fill sA[k][o] = c1[o][ch*64 + k]  (coalesced LDG along k)
        {
            int k  = t & 63;
            int o0 = t >> 6;               // 0 or 1
            const float* cp = c1 + (size_t)ch * KC + k;
            #pragma unroll 8
            for (int j = 0; j < 32; j++) {
                int o = o0 + 2 * j;
                sA[k * 68 + o] = __ldg(cp + (size_t)o * 1600);
            }
        }
        // fill sB[k][row=t]: RBF basis on the fly
        #pragma unroll
        for (int ii = 0; ii < 4; ii++) {
            float xn = (xp[(ch * 4 + ii) * BM + t] - mu) * sc;
            #pragma unroll
            for (int n = 0; n < NB; n++) {
                float d = xn - ctr[n];
                sB[(ii * NB + n) * BM + t] = __expf(K2 * d * d);
            }
        }
        __syncthreads();

        // 8x8 register-tile GEMM with packed f32x2 FMAs
        #pragma unroll 8
        for (int k = 0; k < KC; k++) {
            ulonglong2 a01 = *(const ulonglong2*)&sA[k * 68 + tc];
            ulonglong2 a23 = *(const ulonglong2*)&sA[k * 68 + tc + 4];
            float4 b0 = *(const float4*)&sB[k * BM + tr];
            float4 b1 = *(const float4*)&sB[k * BM + tr + 4];
            float bb[8] = {b0.x, b0.y, b0.z, b0.w, b1.x, b1.y, b1.z, b1.w};
            #pragma unroll
            for (int r = 0; r < 8; r++) {
                unsigned long long bd = pk2(bb[r], bb[r]);
                fma2(acc[r][0], bd, a01.x);
                fma2(acc[r][1], bd, a01.y);
                fma2(acc[r][2], bd, a23.x);
                fma2(acc[r][3], bd, a23.y);
            }
        }
    }
    __syncthreads();   // all GEMM reads done before overwriting sA/sB with sh

    // epilogue: tanh into sh[row][65]
    #pragma unroll
    for (int r = 0; r < 8; r++) {
        #pragma unroll
        for (int c4 = 0; c4 < 4; c4++) {
            float v0, v1;
            upk2(acc[r][c4], v0, v1);
            sh[(tr + r) * 65 + tc + c4 * 2 + 0] = tanhf(v0);
            sh[(tr + r) * 65 + tc + c4 * 2 + 1] = tanhf(v1);
        }
    }
    // stage c2 into smem (xp region is dead now)
    for (int e = t; e < OUTD * HID * NB; e += NTHR) c2s[e] = __ldg(c2 + e);
    __syncthreads();

    // ---------------- Phase 3: norm2 + basis2 + GEMM2 (thread t = row t) ----------------
    {
        float m2 = 0.f;
        #pragma unroll 8
        for (int j = 0; j < HID; j++) m2 += sh[t * 65 + j];
        m2 *= (1.0f / HID);
        float v2 = 0.f;
        #pragma unroll 8
        for (int j = 0; j < HID; j++) { float d = sh[t * 65 + j] - m2; v2 += d * d; }
        v2 *= (1.0f / (HID - 1));
        const float s2 = 1.0f / (sqrtf(v2) + 1e-6f);

        float o[OUTD] = {0.f, 0.f, 0.f, 0.f, 0.f};
        #pragma unroll 4
        for (int j = 0; j < HID; j++) {
            float xn = (sh[t * 65 + j] - m2) * s2;
            #pragma unroll
            for (int n = 0; n < NB; n++) {
                float d = xn - ctr[n];
                float e = __expf(K2 * d * d);
                #pragma unroll
                for (int q = 0; q < OUTD; q++)
                    o[q] += e * c2s[q * (HID * NB) + j * NB + n];
            }
        }
        float* op = out + ((size_t)blk * BM + t) * OUTD;
        #pragma unroll
        for (int q = 0; q < OUTD; q++) op[q] = o[q];
    }
}

extern "C" void kernel_launch(void* const* d_in, const int* in_sizes, int n_in,
                              void* d_out, int out_size)
{
    const float* x       = (const float*)d_in[0];   // [65536,1000]
    const float* c1      = (const float*)d_in[1];   // [64,100,16]
    const float* c2      = (const float*)d_in[2];   // [5,64,16]
    const float* centers = (const float*)d_in[3];   // [16]
    float* out = (float*)d_out;

    cudaFuncSetAttribute(kan_fused_kernel,
                         cudaFuncAttributeMaxDynamicSharedMemorySize, SMEM_BYTES);
    kan_fused_kernel<<<BATCH / BM, NTHR, SMEM_BYTES>>>(x, c1, c2, centers, out);
}